// round 10
// baseline (speedup 1.0000x reference)
#include <cuda_runtime.h>

#define NBLK 144
#define NGATE 128
#define NATT 16
#define NT 1024

__device__ float g_ct[524288];    // [B=32][L=64][A=256]
__device__ float g_w1hT[131072];  // [A=256][H=512] transposed att_h_W1
__device__ float g_h[2 * 16384];  // double-buffered h: [parity][32][512]
__device__ float g_c[16384];
__device__ float g_cv[16384];
__device__ unsigned g_flag[NBLK * 8];   // monotonic counters (never reset)

struct P {
    const float *X, *ctx, *mask; const int* cmask;
    const float *W[4], *U[4], *C[4], *bs[4];
    const float *w1c, *w1h, *b1, *w2, *b2;
    float *oh, *oc, *octx;
};

typedef unsigned long long ull;

__device__ __forceinline__ float fsig(float x)  { return 1.f / (1.f + __expf(-x)); }
__device__ __forceinline__ float ftanh(float x) { return 1.f - 2.f / (1.f + __expf(2.f * x)); }
__device__ __forceinline__ float tanha(float x) { float y; asm("tanh.approx.f32 %0, %1;" : "=f"(y) : "f"(x)); return y; }
__device__ __forceinline__ ull fpack(float lo, float hi) {
    ull r; asm("mov.b64 %0, {%1, %2};" : "=l"(r) : "f"(lo), "f"(hi)); return r;
}
__device__ __forceinline__ ull fpack1(float v) {
    ull r; asm("mov.b64 %0, {%1, %1};" : "=l"(r) : "f"(v)); return r;
}
__device__ __forceinline__ void funpack(ull v, float& lo, float& hi) {
    asm("mov.b64 {%0, %1}, %2;" : "=f"(lo), "=f"(hi) : "l"(v));
}
__device__ __forceinline__ void fma2(ull& acc, ull a, ull b) {
    asm("fma.rn.f32x2 %0, %1, %2, %0;" : "+l"(acc) : "l"(a), "l"(b));
}

// Full prologue barrier (all NBLK blocks), monotonic value fv.
__device__ __forceinline__ void gridbar_full(unsigned fv) {
    __syncthreads();
    if (threadIdx.x < 32) {
        if (threadIdx.x == 0) {
            __threadfence();
            *(volatile unsigned*)&g_flag[blockIdx.x * 8] = fv;
        }
        for (;;) {
            bool ok = true;
            #pragma unroll
            for (int j = 0; j < 5; ++j) {
                int bk = threadIdx.x + j * 32;
                if (bk < NBLK) ok &= (*(volatile unsigned*)&g_flag[bk * 8] >= fv);
            }
            if (__all_sync(0xffffffffu, ok)) break;
            __nanosleep(32);
        }
        __threadfence();
    }
    __syncthreads();
}

// Wait until flags[lo .. lo+cnt) are all >= v. No arrival store.
template <int CNT>
__device__ __forceinline__ void wait_flags(int lo, unsigned v) {
    __syncthreads();
    if (threadIdx.x < 32) {
        for (;;) {
            bool ok = true;
            #pragma unroll
            for (int j = 0; j < (CNT + 31) / 32; ++j) {
                int bk = threadIdx.x + j * 32;
                if (bk < CNT) ok &= (*(volatile unsigned*)&g_flag[(lo + bk) * 8] >= v);
            }
            if (__all_sync(0xffffffffu, ok)) break;
            __nanosleep(32);
        }
        __threadfence();
    }
    __syncthreads();
}

// Publish own flag = v (after all threads' prior STGs).
__device__ __forceinline__ void publish(unsigned v) {
    __syncthreads();
    if (threadIdx.x == 0) {
        __threadfence();
        *(volatile unsigned*)&g_flag[blockIdx.x * 8] = v;
    }
}

// prologue ctx_trans; csm[512], rsm[4*260]
__device__ void ct_task(const P& p, float* csm, float* rsm, int blk, int tid) {
    const int a = tid & 255, kq = tid >> 8;   // kq 0..3
    for (int tt = blk; tt < 2048; tt += NBLK) {
        int b = tt >> 6, l = tt & 63;
        __syncthreads();
        if (tid < 512) csm[tid] = p.ctx[(b * 64 + l) * 512 + tid];
        __syncthreads();
        float acc = 0.f;
        #pragma unroll 8
        for (int i = 0; i < 128; ++i) {
            int k = kq * 128 + i;
            acc = fmaf(p.w1c[k * 256 + a], csm[k], acc);
        }
        rsm[kq * 260 + a] = acc;
        __syncthreads();
        if (tid < 256)
            g_ct[(b * 64 + l) * 256 + tid] =
                rsm[tid] + rsm[260 + tid] + rsm[520 + tid] + rsm[780 + tid] + p.b1[tid];
        __syncthreads();
    }
}

// stage 32x512 rows into vs[32][513]
__device__ __forceinline__ void gstage(float* vs, const float* src, int stride, int tid) {
    __syncthreads();
    #pragma unroll
    for (int j = 0; j < 4; ++j) {
        int i4 = tid + j * NT;
        int bb = i4 >> 7;
        int k4 = (i4 & 127) * 4;
        float4 v = __ldcg((const float4*)(src + bb * stride + k4));
        float* d = vs + bb * 513 + k4;
        d[0] = v.x; d[1] = v.y; d[2] = v.z; d[3] = v.w;
    }
    __syncthreads();
}

// 16 k per thread; acc: 8 packed f32x2 pairs
__device__ __forceinline__ void gpass(ull acc[8], const float* vs, const float* wsm,
                                      int kq, int b) {
    const float* vb = vs + b * 513;
    #pragma unroll 4
    for (int i = 0; i < 16; ++i) {
        int k = i * 32 + kq;
        ull vv = fpack1(vb[k]);
        #pragma unroll
        for (int g = 0; g < 4; ++g) {
            ulonglong2 w = *(const ulonglong2*)(wsm + (g * 512 + k) * 4);
            fma2(acc[g * 2],     w.x, vv);
            fma2(acc[g * 2 + 1], w.y, vv);
        }
    }
}

__device__ void gate_role(const P& p, char* smem, int blk, int tid, unsigned base) {
    float* wsm = (float*)smem;        // 24576 f [mat][g][k][4]
    float* vs  = wsm + 24576;         // 16416 f [32][513]
    float* red = vs;                  // alias
    float* csm = vs;                  // prologue alias
    float* rsm = vs + 512;
    const int hc = blk, b = tid & 31, kq = tid >> 5;   // kq 0..31

    for (int i = tid; i < 24576; i += NT) {
        int j = i & 3, k = (i >> 2) & 511, g = (i >> 11) & 3, m = i >> 13;
        const float* s = (m == 0) ? p.W[g] : (m == 1) ? p.U[g] : p.C[g];
        wsm[i] = s[k * 512 + hc * 4 + j];
    }
    {
        int zi = blk * NT + tid;
        if (zi < 32768) g_h[zi] = 0.f;
        if (zi < 16384) g_c[zi] = 0.f;
    }
    for (int i = blk * NT + tid; i < 131072; i += NBLK * NT) {
        int k = i >> 8, aa = i & 255;
        g_w1hT[aa * 512 + k] = p.w1h[i];
    }
    ct_task(p, csm, rsm, blk, tid);
    gridbar_full(base + 1);

    ull b0[8];
    #pragma unroll
    for (int g = 0; g < 4; ++g) {
        float4 bf = *(const float4*)(p.bs[g] + hc * 4);
        b0[g * 2]     = fpack(bf.x, bf.y);
        b0[g * 2 + 1] = fpack(bf.z, bf.w);
    }
    const ull zz = fpack(0.f, 0.f);

    unsigned sv = base + 1;
    for (int t = 0; t < 128; ++t, ++sv) {
        const float* hprev = g_h + (t & 1) * 16384;
        float* hnew        = g_h + ((t & 1) ^ 1) * 16384;
        gstage(vs, p.X + t * 512, 65536, tid);    // pre-stage X(t) behind the wait
        wait_flags<NGATE>(0, sv);                 // all h(t-1) slices published
        ull acc[8];
        #pragma unroll
        for (int q = 0; q < 8; ++q) acc[q] = (kq == 0) ? b0[q] : zz;
        gpass(acc, vs, wsm, kq, b);               // x_t @ W
        gstage(vs, hprev, 512, tid);
        gpass(acc, vs, wsm + 8192, kq, b);        // h @ U
        wait_flags<NATT>(NGATE, sv + 1);          // cv(t) published
        gstage(vs, g_cv, 512, tid);
        gpass(acc, vs, wsm + 16384, kq, b);       // cv @ C
        __syncthreads();
        float av4[4][4];
        #pragma unroll
        for (int g = 0; g < 4; ++g) {
            funpack(acc[g * 2],     av4[g][0], av4[g][1]);
            funpack(acc[g * 2 + 1], av4[g][2], av4[g][3]);
        }
        if (kq >= 16) {
            int q = kq - 16;
            #pragma unroll
            for (int g = 0; g < 4; ++g)
                #pragma unroll
                for (int j = 0; j < 4; ++j)
                    red[((g * 4 + j) * 16 + q) * 33 + b] = av4[g][j];
        }
        __syncthreads();
        if (kq < 16) {
            #pragma unroll
            for (int g = 0; g < 4; ++g)
                #pragma unroll
                for (int j = 0; j < 4; ++j)
                    red[((g * 4 + j) * 16 + kq) * 33 + b] += av4[g][j];
        }
        __syncthreads();
        if (tid < 128) {
            int bb = tid >> 2, j = tid & 3, h = hc * 4 + j;
            float pre[4];
            #pragma unroll
            for (int g = 0; g < 4; ++g) {
                int o = g * 4 + j;
                float s = 0.f;
                #pragma unroll
                for (int q = 0; q < 16; ++q) s += red[(o * 16 + q) * 33 + bb];
                pre[g] = s;
            }
            float iv = fsig(pre[0]), fv = fsig(pre[1]);
            float gv = ftanh(pre[2]), ov = fsig(pre[3]);
            float co = g_c[bb * 512 + h];
            float ho = __ldcg(&hprev[bb * 512 + h]);
            float cn = fv * co + iv * gv;
            float hn = ov * ftanh(cn);
            float m = p.mask[bb * 128 + t];
            hn = (1.f - m) * ho + m * hn;
            cn = (1.f - m) * co + m * cn;
            hnew[bb * 512 + h] = hn;
            g_c[bb * 512 + h] = cn;
            p.oh[(bb * 128 + t) * 512 + h] = hn;
            p.oc[(bb * 128 + t) * 512 + h] = cn;
        }
        publish(sv + 1);
    }
}

__device__ void att_role(const P& p, char* smem, int blk, int tid, unsigned base) {
    float* ctsm = (float*)smem;       // 32768 f [2][64][256]
    float* hsm  = ctsm + 32768;       // 1024
    float* redh = hsm + 1024;         // 2056: [2][4][257]
    float* hwsm = redh + 2056;        // 512: [2][256]
    float* w2sm = hwsm + 512;         // 256
    float* esm  = w2sm + 256;         // 128
    float* av   = esm + 128;          // 128
    float* ssum = av + 128;           // 16
    float* csm  = ctsm;               // prologue alias
    float* rsm  = ctsm + 512;
    const int b0 = (blk - NGATE) * 2;
    const int a = tid & 255, kq = tid >> 8;   // kq 0..3
    const int ww = tid >> 5, lane = tid & 31;

    ct_task(p, csm, rsm, blk, tid);
    gridbar_full(base + 1);
    for (int i = tid; i < 32768; i += NT) ctsm[i] = __ldcg(&g_ct[b0 * 16384 + i]);
    if (tid < 256) w2sm[tid] = p.w2[tid];
    const float b2v = p.b2[0];
    const ull zz = fpack(0.f, 0.f);

    unsigned sv = base + 1;
    for (int t = 0; t < 128; ++t, ++sv) {
        wait_flags<NGATE>(0, sv);                 // h(t-1) published
        const float* hprev = g_h + (t & 1) * 16384;
        hsm[tid] = __ldcg(&hprev[b0 * 512 + tid]);
        __syncthreads();
        // hW with transposed weights: thread (a, kq) covers k in [kq*128, kq*128+128) as pairs
        ull ac0 = zz, ac1 = zz;
        const ull* wp  = (const ull*)(g_w1hT + a * 512 + kq * 128);
        const float* h0p = hsm + kq * 128;
        const float* h1p = hsm + 512 + kq * 128;
        #pragma unroll 8
        for (int i = 0; i < 64; ++i) {
            ull w = __ldg(wp + i);
            fma2(ac0, w, *(const ull*)(h0p + 2 * i));
            fma2(ac1, w, *(const ull*)(h1p + 2 * i));
        }
        {
            float x, y;
            funpack(ac0, x, y);  redh[kq * 257 + a] = x + y;
            funpack(ac1, x, y);  redh[1028 + kq * 257 + a] = x + y;
        }
        __syncthreads();
        if (tid < 512) {
            int bb = tid >> 8, aa = tid & 255;
            const float* r = redh + bb * 1028;
            hwsm[bb * 256 + aa] = r[aa] + r[257 + aa] + r[514 + aa] + r[771 + aa];
        }
        __syncthreads();
        // scores: warp ww -> bb = ww>>4, l = (ww&15)*4 + lq ; tanh.approx
        {
            int bb = ww >> 4;
            #pragma unroll
            for (int lq = 0; lq < 4; ++lq) {
                int l = (ww & 15) * 4 + lq;
                float s = 0.f;
                #pragma unroll
                for (int j = 0; j < 8; ++j) {
                    int aa = j * 32 + lane;
                    float x = ctsm[(bb * 64 + l) * 256 + aa] + hwsm[bb * 256 + aa];
                    s = fmaf(tanha(x), w2sm[aa], s);
                }
                #pragma unroll
                for (int o = 16; o; o >>= 1) s += __shfl_xor_sync(0xffffffffu, s, o);
                if (lane == 0)
                    esm[bb * 64 + l] = __expf(s + b2v) * (float)__ldg(&p.cmask[(b0 + bb) * 64 + l]);
            }
        }
        __syncthreads();
        if (tid < 2) {
            float s = 0.f;
            for (int l = 0; l < 64; ++l) s += esm[tid * 64 + l];
            ssum[tid] = s;
        }
        __syncthreads();
        if (tid < 128) av[tid] = esm[tid] / ssum[tid >> 6];
        __syncthreads();
        // ctx_vec: thread owns (bb = tid>>9, d = tid&511)
        {
            int bb = tid >> 9, d = tid & 511;
            float c = 0.f;
            const float* cp = p.ctx + ((b0 + bb) * 64) * 512 + d;
            const float* ap = av + bb * 64;
            #pragma unroll 8
            for (int l = 0; l < 64; ++l)
                c = fmaf(ap[l], __ldg(cp + l * 512), c);
            g_cv[(b0 + bb) * 512 + d] = c;
            p.octx[((b0 + bb) * 128 + t) * 512 + d] = c;
        }
        publish(sv + 1);                          // cv(t) ready
    }
}

extern "C" __global__ void __launch_bounds__(NT, 1) cond_lstm(P p) {
    extern __shared__ char smem[];
    const unsigned base = *(volatile unsigned*)&g_flag[blockIdx.x * 8];
    if (blockIdx.x < NGATE) gate_role(p, smem, blockIdx.x, threadIdx.x, base);
    else                    att_role(p, smem, blockIdx.x, threadIdx.x, base);
}

#define SMEM_BYTES 163968

extern "C" void kernel_launch(void* const* d_in, const int* in_sizes, int n_in,
                              void* d_out, int out_size) {
    (void)in_sizes; (void)n_in; (void)out_size;
    P p;
    p.X     = (const float*)d_in[0];
    p.ctx   = (const float*)d_in[1];
    p.mask  = (const float*)d_in[2];
    p.cmask = (const int*)d_in[3];
    for (int g = 0; g < 4; ++g) {
        p.W[g]  = (const float*)d_in[4 + 4 * g];
        p.U[g]  = (const float*)d_in[5 + 4 * g];
        p.C[g]  = (const float*)d_in[6 + 4 * g];
        p.bs[g] = (const float*)d_in[7 + 4 * g];
    }
    p.w1c = (const float*)d_in[20];
    p.w1h = (const float*)d_in[21];
    p.b1  = (const float*)d_in[22];
    p.w2  = (const float*)d_in[23];
    p.b2  = (const float*)d_in[24];
    float* out = (float*)d_out;
    p.oh   = out;
    p.oc   = out + 32 * 128 * 512;
    p.octx = out + 2 * 32 * 128 * 512;

    cudaFuncSetAttribute(cond_lstm, cudaFuncAttributeMaxDynamicSharedMemorySize, SMEM_BYTES);
    cond_lstm<<<NBLK, NT, SMEM_BYTES>>>(p);
}

// round 11
// speedup vs baseline: 1.9865x; 1.9865x over previous
#include <cuda_runtime.h>

#define NBLK 144
#define NGATE 128
#define NATT 16
#define NT 1024

__device__ float g_ct[524288];    // [B=32][L=64][A=256]
__device__ float g_h[16384];      // [32][512]
__device__ float g_c[16384];
__device__ float g_cv[16384];
__device__ float g_hwp[131072];   // hW partials [16 j][32 b][256 a]
__device__ unsigned g_flag[NBLK * 8];   // monotonic (never reset)
__device__ unsigned g_aflag[NATT * 8];  // att-only monotonic flags

struct P {
    const float *X, *ctx, *mask; const int* cmask;
    const float *W[4], *U[4], *C[4], *bs[4];
    const float *w1c, *w1h, *b1, *w2, *b2;
    float *oh, *oc, *octx;
};

typedef unsigned long long ull;

__device__ __forceinline__ float fsig(float x)  { return 1.f / (1.f + __expf(-x)); }
__device__ __forceinline__ float ftanh(float x) { return 1.f - 2.f / (1.f + __expf(2.f * x)); }
__device__ __forceinline__ float tanha(float x) { float y; asm("tanh.approx.f32 %0, %1;" : "=f"(y) : "f"(x)); return y; }
__device__ __forceinline__ ull fpack(float lo, float hi) {
    ull r; asm("mov.b64 %0, {%1, %2};" : "=l"(r) : "f"(lo), "f"(hi)); return r;
}
__device__ __forceinline__ ull fpack1(float v) {
    ull r; asm("mov.b64 %0, {%1, %1};" : "=l"(r) : "f"(v)); return r;
}
__device__ __forceinline__ void funpack(ull v, float& lo, float& hi) {
    asm("mov.b64 {%0, %1}, %2;" : "=f"(lo), "=f"(hi) : "l"(v));
}
__device__ __forceinline__ void fma2(ull& acc, ull a, ull b) {
    asm("fma.rn.f32x2 %0, %1, %2, %0;" : "+l"(acc) : "l"(a), "l"(b));
}

// Full grid barrier, monotonic value fv (R9-proven).
__device__ __forceinline__ void gridbar(unsigned fv) {
    __syncthreads();
    if (threadIdx.x < 32) {
        if (threadIdx.x == 0) {
            __threadfence();
            *(volatile unsigned*)&g_flag[blockIdx.x * 8] = fv;
        }
        for (;;) {
            bool ok = true;
            #pragma unroll
            for (int j = 0; j < 5; ++j) {
                int bk = threadIdx.x + j * 32;
                if (bk < NBLK) ok &= (*(volatile unsigned*)&g_flag[bk * 8] >= fv);
            }
            if (__all_sync(0xffffffffu, ok)) break;
            __nanosleep(32);
        }
        __threadfence();
    }
    __syncthreads();
}

// Att-only barrier on g_aflag (16 blocks), monotonic value av.
__device__ __forceinline__ void attbar(int slot, unsigned av) {
    __syncthreads();
    if (threadIdx.x < 32) {
        if (threadIdx.x == 0) {
            __threadfence();
            *(volatile unsigned*)&g_aflag[slot * 8] = av;
        }
        for (;;) {
            bool ok = true;
            if (threadIdx.x < NATT)
                ok = (*(volatile unsigned*)&g_aflag[threadIdx.x * 8] >= av);
            if (__all_sync(0xffffffffu, ok)) break;
            __nanosleep(32);
        }
        __threadfence();
    }
    __syncthreads();
}

// prologue ctx_trans; csm[512], rsm[4*260]
__device__ void ct_task(const P& p, float* csm, float* rsm, int blk, int tid) {
    const int a = tid & 255, kq = tid >> 8;   // kq 0..3
    for (int tt = blk; tt < 2048; tt += NBLK) {
        int b = tt >> 6, l = tt & 63;
        __syncthreads();
        if (tid < 512) csm[tid] = p.ctx[(b * 64 + l) * 512 + tid];
        __syncthreads();
        float acc = 0.f;
        #pragma unroll 8
        for (int i = 0; i < 128; ++i) {
            int k = kq * 128 + i;
            acc = fmaf(p.w1c[k * 256 + a], csm[k], acc);
        }
        rsm[kq * 260 + a] = acc;
        __syncthreads();
        if (tid < 256)
            g_ct[(b * 64 + l) * 256 + tid] =
                rsm[tid] + rsm[260 + tid] + rsm[520 + tid] + rsm[780 + tid] + p.b1[tid];
        __syncthreads();
    }
}

// stage 32x512 rows into vs[32][513]
__device__ __forceinline__ void gstage(float* vs, const float* src, int stride, int tid) {
    __syncthreads();
    #pragma unroll
    for (int j = 0; j < 4; ++j) {
        int i4 = tid + j * NT;
        int bb = i4 >> 7;
        int k4 = (i4 & 127) * 4;
        float4 v = __ldcg((const float4*)(src + bb * stride + k4));
        float* d = vs + bb * 513 + k4;
        d[0] = v.x; d[1] = v.y; d[2] = v.z; d[3] = v.w;
    }
    __syncthreads();
}

// 16 k per thread; acc: 8 packed f32x2 pairs
__device__ __forceinline__ void gpass(ull acc[8], const float* vs, const float* wsm,
                                      int kq, int b) {
    const float* vb = vs + b * 513;
    #pragma unroll 4
    for (int i = 0; i < 16; ++i) {
        int k = i * 32 + kq;
        ull vv = fpack1(vb[k]);
        #pragma unroll
        for (int g = 0; g < 4; ++g) {
            ulonglong2 w = *(const ulonglong2*)(wsm + (g * 512 + k) * 4);
            fma2(acc[g * 2],     w.x, vv);
            fma2(acc[g * 2 + 1], w.y, vv);
        }
    }
}

__device__ void gate_role(const P& p, char* smem, int blk, int tid, unsigned base) {
    float* wsm = (float*)smem;        // 24576 f [mat][g][k][4]
    float* vs  = wsm + 24576;         // 16416 f [32][513]
    float* red = vs;                  // alias
    float* csm = vs;                  // prologue alias
    float* rsm = vs + 512;
    const int hc = blk, b = tid & 31, kq = tid >> 5;   // kq 0..31

    for (int i = tid; i < 24576; i += NT) {
        int j = i & 3, k = (i >> 2) & 511, g = (i >> 11) & 3, m = i >> 13;
        const float* s = (m == 0) ? p.W[g] : (m == 1) ? p.U[g] : p.C[g];
        wsm[i] = s[k * 512 + hc * 4 + j];
    }
    {
        int zi = blk * NT + tid;
        if (zi < 16384) { g_h[zi] = 0.f; g_c[zi] = 0.f; }
    }
    ct_task(p, csm, rsm, blk, tid);
    gridbar(base + 1);

    ull b0[8];
    #pragma unroll
    for (int g = 0; g < 4; ++g) {
        float4 bf = *(const float4*)(p.bs[g] + hc * 4);
        b0[g * 2]     = fpack(bf.x, bf.y);
        b0[g * 2 + 1] = fpack(bf.z, bf.w);
    }
    const ull zz = fpack(0.f, 0.f);

    unsigned bar = base + 2;
    for (int t = 0; t < 128; ++t) {
        gstage(vs, p.X + t * 512, 65536, tid);    // pre-stage X(t) behind barrier wait
        gridbar(bar); bar++;                      // h,c,cv of t-1 sealed
        ull acc[8];
        #pragma unroll
        for (int q = 0; q < 8; ++q) acc[q] = (kq == 0) ? b0[q] : zz;
        gpass(acc, vs, wsm, kq, b);               // x_t @ W
        gstage(vs, g_h, 512, tid);
        gpass(acc, vs, wsm + 8192, kq, b);        // h @ U
        gridbar(bar); bar++;                      // cv ready
        gstage(vs, g_cv, 512, tid);
        gpass(acc, vs, wsm + 16384, kq, b);       // cv @ C
        __syncthreads();
        float av4[4][4];
        #pragma unroll
        for (int g = 0; g < 4; ++g) {
            funpack(acc[g * 2],     av4[g][0], av4[g][1]);
            funpack(acc[g * 2 + 1], av4[g][2], av4[g][3]);
        }
        if (kq >= 16) {
            int q = kq - 16;
            #pragma unroll
            for (int g = 0; g < 4; ++g)
                #pragma unroll
                for (int j = 0; j < 4; ++j)
                    red[((g * 4 + j) * 16 + q) * 33 + b] = av4[g][j];
        }
        __syncthreads();
        if (kq < 16) {
            #pragma unroll
            for (int g = 0; g < 4; ++g)
                #pragma unroll
                for (int j = 0; j < 4; ++j)
                    red[((g * 4 + j) * 16 + kq) * 33 + b] += av4[g][j];
        }
        __syncthreads();
        if (tid < 128) {
            int bb = tid >> 2, j = tid & 3, h = hc * 4 + j;
            float pre[4];
            #pragma unroll
            for (int g = 0; g < 4; ++g) {
                int o = g * 4 + j;
                float s = 0.f;
                #pragma unroll
                for (int q = 0; q < 16; ++q) s += red[(o * 16 + q) * 33 + bb];
                pre[g] = s;
            }
            float iv = fsig(pre[0]), fv = fsig(pre[1]);
            float gv = ftanh(pre[2]), ov = fsig(pre[3]);
            float co = __ldcg(&g_c[bb * 512 + h]), ho = __ldcg(&g_h[bb * 512 + h]);
            float cn = fv * co + iv * gv;
            float hn = ov * ftanh(cn);
            float m = p.mask[bb * 128 + t];
            hn = (1.f - m) * ho + m * hn;
            cn = (1.f - m) * co + m * cn;
            g_h[bb * 512 + h] = hn;
            g_c[bb * 512 + h] = cn;
            p.oh[(bb * 128 + t) * 512 + h] = hn;
            p.oc[(bb * 128 + t) * 512 + h] = cn;
        }
    }
}

__device__ void att_role(const P& p, char* smem, int blk, int tid,
                         unsigned base, unsigned base_a) {
    float* ctsm = (float*)smem;       // 32768 f [2][64][256]
    float* wk   = ctsm + 32768;       // 8192 f: w1h rows [32 k][256 a] for own slice
    float* hk   = wk + 8192;          // 1056 f: [32 b][33]
    float* hwsm = hk + 1056;          // 512 f: [2][256]
    float* w2sm = hwsm + 512;         // 256
    float* esm  = w2sm + 256;         // 128
    float* av   = esm + 128;          // 128
    float* ssum = av + 128;           // 16
    float* csm  = ctsm;               // prologue alias
    float* rsm  = ctsm + 512;
    const int jslot = blk - NGATE;    // 0..15
    const int b0 = jslot * 2;
    const int a2 = tid & 127, bq = tid >> 7;   // a-pair, b-quarter 0..7
    const int ww = tid >> 5, lane = tid & 31;

    ct_task(p, csm, rsm, blk, tid);
    // own w1h k-slice: rows [32*jslot, +32) of [512][256]
    for (int i = tid; i < 8192; i += NT)
        wk[i] = p.w1h[jslot * 8192 + i];
    gridbar(base + 1);
    for (int i = tid; i < 32768; i += NT) ctsm[i] = __ldcg(&g_ct[b0 * 16384 + i]);
    if (tid < 256) w2sm[tid] = p.w2[tid];
    const float b2v = p.b2[0];
    const ull zz = fpack(0.f, 0.f);

    unsigned bar = base + 2;
    for (int t = 0; t < 128; ++t) {
        gridbar(bar); bar++;                      // h(t-1) sealed
        // stage h[all b][own 32 k]
        { int b = tid >> 5, kk = tid & 31;
          hk[b * 33 + kk] = __ldcg(&g_h[b * 512 + jslot * 32 + kk]); }
        __syncthreads();
        // partial hW: thread (a2, bq) covers b in {bq, bq+8, bq+16, bq+24}
        ull acc[4];
        #pragma unroll
        for (int i = 0; i < 4; ++i) acc[i] = zz;
        #pragma unroll 8
        for (int k = 0; k < 32; ++k) {
            ull w = *(const ull*)&wk[k * 256 + a2 * 2];
            #pragma unroll
            for (int i = 0; i < 4; ++i)
                fma2(acc[i], w, fpack1(hk[(bq + i * 8) * 33 + k]));
        }
        #pragma unroll
        for (int i = 0; i < 4; ++i)
            *(ull*)&g_hwp[jslot * 8192 + (bq + i * 8) * 256 + a2 * 2] = acc[i];
        attbar(jslot, base_a + 1 + (unsigned)t);   // all partials ready
        // hw = sum of 16 partials for own 2 batches
        if (tid < 512) {
            int bb = tid >> 8, aa = tid & 255;
            float s = 0.f;
            #pragma unroll
            for (int jj = 0; jj < 16; ++jj)
                s += __ldcg(&g_hwp[jj * 8192 + (b0 + bb) * 256 + aa]);
            hwsm[bb * 256 + aa] = s;
        }
        __syncthreads();
        // scores: warp ww -> bb = ww>>4, l = (ww&15)*4 + lq ; tanh.approx
        {
            int bb = ww >> 4;
            #pragma unroll
            for (int lq = 0; lq < 4; ++lq) {
                int l = (ww & 15) * 4 + lq;
                float s = 0.f;
                #pragma unroll
                for (int j = 0; j < 8; ++j) {
                    int aa = j * 32 + lane;
                    float x = ctsm[(bb * 64 + l) * 256 + aa] + hwsm[bb * 256 + aa];
                    s = fmaf(tanha(x), w2sm[aa], s);
                }
                #pragma unroll
                for (int o = 16; o; o >>= 1) s += __shfl_xor_sync(0xffffffffu, s, o);
                if (lane == 0)
                    esm[bb * 64 + l] = __expf(s + b2v) * (float)__ldg(&p.cmask[(b0 + bb) * 64 + l]);
            }
        }
        __syncthreads();
        if (tid < 2) {
            float s = 0.f;
            for (int l = 0; l < 64; ++l) s += esm[tid * 64 + l];
            ssum[tid] = s;
        }
        __syncthreads();
        if (tid < 128) av[tid] = esm[tid] / ssum[tid >> 6];
        __syncthreads();
        // ctx_vec: thread owns (bb = tid>>9, d = tid&511)
        {
            int bb = tid >> 9, d = tid & 511;
            float c = 0.f;
            const float* cp = p.ctx + ((b0 + bb) * 64) * 512 + d;
            const float* ap = av + bb * 64;
            #pragma unroll 8
            for (int l = 0; l < 64; ++l)
                c = fmaf(ap[l], __ldg(cp + l * 512), c);
            g_cv[(b0 + bb) * 512 + d] = c;
            p.octx[((b0 + bb) * 128 + t) * 512 + d] = c;
        }
        gridbar(bar); bar++;                      // cv published
    }
}

extern "C" __global__ void __launch_bounds__(NT, 1) cond_lstm(P p) {
    extern __shared__ char smem[];
    const unsigned base = *(volatile unsigned*)&g_flag[blockIdx.x * 8];
    if (blockIdx.x < NGATE) {
        gate_role(p, smem, blockIdx.x, threadIdx.x, base);
    } else {
        const unsigned base_a = *(volatile unsigned*)&g_aflag[(blockIdx.x - NGATE) * 8];
        att_role(p, smem, blockIdx.x, threadIdx.x, base, base_a);
    }
}

#define SMEM_BYTES 172288

extern "C" void kernel_launch(void* const* d_in, const int* in_sizes, int n_in,
                              void* d_out, int out_size) {
    (void)in_sizes; (void)n_in; (void)out_size;
    P p;
    p.X     = (const float*)d_in[0];
    p.ctx   = (const float*)d_in[1];
    p.mask  = (const float*)d_in[2];
    p.cmask = (const int*)d_in[3];
    for (int g = 0; g < 4; ++g) {
        p.W[g]  = (const float*)d_in[4 + 4 * g];
        p.U[g]  = (const float*)d_in[5 + 4 * g];
        p.C[g]  = (const float*)d_in[6 + 4 * g];
        p.bs[g] = (const float*)d_in[7 + 4 * g];
    }
    p.w1c = (const float*)d_in[20];
    p.w1h = (const float*)d_in[21];
    p.b1  = (const float*)d_in[22];
    p.w2  = (const float*)d_in[23];
    p.b2  = (const float*)d_in[24];
    float* out = (float*)d_out;
    p.oh   = out;
    p.oc   = out + 32 * 128 * 512;
    p.octx = out + 2 * 32 * 128 * 512;

    cudaFuncSetAttribute(cond_lstm, cudaFuncAttributeMaxDynamicSharedMemorySize, SMEM_BYTES);
    cond_lstm<<<NBLK, NT, SMEM_BYTES>>>(p);
}